// round 9
// baseline (speedup 1.0000x reference)
#include <cuda_runtime.h>
#include <cstdint>

#define NTOK 4096
#define DDIM 1024
#define HDIM 2048
#define NEXP 8

// ---------------- scratch (static __device__, allocation-free) ----------------
__device__ float g_hbuf[(size_t)NEXP * NTOK * HDIM];        // gelu(h) per slot (tf32-rounded)
__device__ float g_ybuf[(size_t)NEXP * NTOK * DDIM];        // expert outputs
__device__ int   g_counts[NEXP];
__device__ int   g_tok [NEXP * NTOK];                       // expert -> token list
__device__ int   g_expi[NTOK * 2];
__device__ int   g_slot[NTOK * 2];
__device__ float g_gate[NTOK * 2];

// ---------------- helpers ----------------
__device__ __forceinline__ uint32_t tf32_bits(float v) {    // round-to-nearest tf32
    uint32_t r;
    asm("cvt.rna.tf32.f32 %0, %1;" : "=r"(r) : "f"(v));
    return r;
}
__device__ __forceinline__ float tf32_round(float v) { return __uint_as_float(tf32_bits(v)); }

__device__ __forceinline__ void cpasync16(void* s, const void* g) {
    uint32_t sa = (uint32_t)__cvta_generic_to_shared(s);
    asm volatile("cp.async.cg.shared.global [%0], [%1], 16;" :: "r"(sa), "l"(g));
}
__device__ __forceinline__ void cp_commit() { asm volatile("cp.async.commit_group;"); }
__device__ __forceinline__ void cp_wait2()  { asm volatile("cp.async.wait_group 2;"); }

__device__ __forceinline__ void mma_tf32(float* c, const uint32_t* a, const uint32_t* b) {
    asm volatile(
        "mma.sync.aligned.m16n8k8.row.col.f32.tf32.tf32.f32 "
        "{%0,%1,%2,%3}, {%4,%5,%6,%7}, {%8,%9}, {%0,%1,%2,%3};"
        : "+f"(c[0]), "+f"(c[1]), "+f"(c[2]), "+f"(c[3])
        : "r"(a[0]), "r"(a[1]), "r"(a[2]), "r"(a[3]), "r"(b[0]), "r"(b[1]));
}

// JAX default gelu: approximate=True (tanh form)
__device__ __forceinline__ float gelu_tanh(float v) {
    float t = tanhf(0.7978845608028654f * (v + 0.044715f * v * v * v));
    return 0.5f * v * (1.0f + t);
}

// ---------------- stage 0: zero counts ----------------
__global__ void zero_counts_kernel() {
    if (threadIdx.x < NEXP) g_counts[threadIdx.x] = 0;
}

// ---------------- stage 1: gating (top-2 softmax + expert lists) ----------------
__global__ void gate_kernel(const float* __restrict__ x, const float* __restrict__ wg) {
    const int n = blockIdx.x;
    const int tid = threadIdx.x;                 // 128 threads
    const float* xr = x + (size_t)n * DDIM;

    float acc[NEXP];
#pragma unroll
    for (int e = 0; e < NEXP; e++) acc[e] = 0.0f;
    for (int d = tid; d < DDIM; d += 128) {
        float xv = xr[d];
        const float* w = wg + d * NEXP;
#pragma unroll
        for (int e = 0; e < NEXP; e++) acc[e] += xv * w[e];
    }
#pragma unroll
    for (int e = 0; e < NEXP; e++) {
#pragma unroll
        for (int o = 16; o > 0; o >>= 1) acc[e] += __shfl_xor_sync(0xffffffffu, acc[e], o);
    }
    __shared__ float sred[4][NEXP];
    const int wid = tid >> 5, lane = tid & 31;
    if (lane == 0) {
#pragma unroll
        for (int e = 0; e < NEXP; e++) sred[wid][e] = acc[e];
    }
    __syncthreads();
    if (tid == 0) {
        float lg[NEXP];
#pragma unroll
        for (int e = 0; e < NEXP; e++)
            lg[e] = sred[0][e] + sred[1][e] + sred[2][e] + sred[3][e];
        int i0 = 0;
#pragma unroll
        for (int e = 1; e < NEXP; e++) if (lg[e] > lg[i0]) i0 = e;
        int i1 = (i0 == 0) ? 1 : 0;
#pragma unroll
        for (int e = 0; e < NEXP; e++) if (e != i0 && lg[e] > lg[i1]) i1 = e;
        float e1 = __expf(lg[i1] - lg[i0]);
        float inv = 1.0f / (1.0f + e1);

        int s0 = atomicAdd(&g_counts[i0], 1);
        int s1 = atomicAdd(&g_counts[i1], 1);
        g_tok[i0 * NTOK + s0] = n;
        g_tok[i1 * NTOK + s1] = n;
        g_expi[n * 2 + 0] = i0;  g_slot[n * 2 + 0] = s0;  g_gate[n * 2 + 0] = inv;
        g_expi[n * 2 + 1] = i1;  g_slot[n * 2 + 1] = s1;  g_gate[n * 2 + 1] = e1 * inv;
    }
}

// ---------------- stages 2/3: grouped GEMM, tf32 mma.sync ----------------
// CTA tile 128(tokens) x 256(cols), BK=16, 4-stage cp.async pipeline.
// 512 threads = 16 warps in a 2x8 grid, 64x32 per warp (4 warps/SMSP for
// latency hiding; this is the occupancy fix for tensor=44.5% @ 2 warps/SMSP).
// One __syncthreads per k-iter; operands tf32-rounded in-register after LDS.

#define A_STRIDE 20          // floats per A smem row (pad: conflict-free frag loads)
#define B_STRIDE 264         // floats per B smem row (pad: conflict-free frag loads)
#define A_STAGE  (128 * A_STRIDE)            // 2560 floats
#define B_STAGE  (16 * B_STRIDE)             // 4224 floats
#define SMEM_FLOATS (4 * (A_STAGE + B_STAGE))
#define SMEM_BYTES  (SMEM_FLOATS * 4)        // 108,544 B

template <int PHASE>
__global__ void __launch_bounds__(512, 1) ffn_gemm_kernel(
    const float* __restrict__ x, const float* __restrict__ w_all,
    const float* __restrict__ bias_all) {
    constexpr int KD   = (PHASE == 1) ? DDIM : HDIM;
    constexpr int NOUT = (PHASE == 1) ? HDIM : DDIM;
    constexpr int KT   = KD / 16;
    constexpr int BN   = 256;

    const int e  = blockIdx.z;
    const int tm = blockIdx.y;
    const int tn = blockIdx.x;
    const int cnt = g_counts[e];
    if (tm * 128 >= cnt) return;
    const int rows = min(128, cnt - tm * 128);

    extern __shared__ float smem[];
    float* const Abase = smem;                       // 4 stages x A_STAGE
    float* const Bbase = smem + 4 * A_STAGE;         // 4 stages x B_STAGE

    const int tid  = threadIdx.x;
    const int lane = tid & 31, wid = tid >> 5;
    const int wm = wid >> 3, wn = wid & 7;           // 2 x 8 warp grid, 64x32 per warp
    const int grp = lane >> 2, tig = lane & 3;

    // ---- per-thread load assignments ----
    // A: 128 rows x 16 k-floats = 512 x 16B chunks; 1 per thread
    const float* ag;
    int aoff;
    const float* wsrc = w_all + (size_t)e * ((size_t)KD * NOUT);
    {
        const int ar = tid >> 2;                     // row 0..127
        const int ac = (tid & 3) * 4;                // k-float offset 0/4/8/12
        if (PHASE == 1) {
            const int tk = g_tok[e * NTOK + tm * 128 + ar];
            ag = x + (size_t)tk * DDIM + ac;
        } else {
            ag = g_hbuf + ((size_t)e * NTOK + tm * 128 + ar) * HDIM + ac;
        }
        aoff = ar * A_STRIDE + ac;
    }
    // B: 16 k-rows x 256 cols = 1024 x 16B chunks; 2 per thread
    const float* bg[2];
    int boff[2];
#pragma unroll
    for (int j = 0; j < 2; j++) {
        const int linear = j * 512 + tid;
        const int br = linear >> 6;                  // k-row 0..15
        const int bc = (linear & 63) * 4;            // col offset 0..252
        bg[j]   = wsrc + (size_t)br * NOUT + (size_t)tn * BN + bc;
        boff[j] = br * B_STRIDE + bc;
    }

    auto issue = [&](int it, int stage) {
        float* As = Abase + stage * A_STAGE;
        float* Bs = Bbase + stage * B_STAGE;
        cpasync16(As + aoff, ag + it * 16);
#pragma unroll
        for (int j = 0; j < 2; j++) cpasync16(Bs + boff[j], bg[j] + (size_t)it * 16 * NOUT);
    };

    float acc[4][4][4];
#pragma unroll
    for (int mi = 0; mi < 4; mi++)
#pragma unroll
        for (int ni = 0; ni < 4; ni++)
#pragma unroll
            for (int q = 0; q < 4; q++) acc[mi][ni][q] = 0.0f;

    // ---- prologue: 3 stages in flight ----
    issue(0, 0); cp_commit();
    issue(1, 1); cp_commit();
    issue(2, 2); cp_commit();

    for (int it = 0; it < KT; it++) {
        const int stage = it & 3;
        cp_wait2();                                  // stage `it` landed
        __syncthreads();                             // everyone done reading stage (it-1)&3
        if (it + 3 < KT) issue(it + 3, (it + 3) & 3);   // overwrites stage (it-1)&3: safe
        cp_commit();                                 // empty commit at tail keeps count math

        const float* As = Abase + stage * A_STAGE;
        const float* Bs = Bbase + stage * B_STAGE;
#pragma unroll
        for (int kk = 0; kk < 2; kk++) {
            uint32_t af[4][4], bf[4][2];
            const int c0 = kk * 8 + tig;
#pragma unroll
            for (int mi = 0; mi < 4; mi++) {
                const int r = wm * 64 + mi * 16 + grp;
                af[mi][0] = tf32_bits(As[r * A_STRIDE + c0]);
                af[mi][1] = tf32_bits(As[(r + 8) * A_STRIDE + c0]);
                af[mi][2] = tf32_bits(As[r * A_STRIDE + c0 + 4]);
                af[mi][3] = tf32_bits(As[(r + 8) * A_STRIDE + c0 + 4]);
            }
#pragma unroll
            for (int ni = 0; ni < 4; ni++) {
                const int nc = wn * 32 + ni * 8 + grp;
                bf[ni][0] = tf32_bits(Bs[(kk * 8 + tig) * B_STRIDE + nc]);
                bf[ni][1] = tf32_bits(Bs[(kk * 8 + 4 + tig) * B_STRIDE + nc]);
            }
#pragma unroll
            for (int mi = 0; mi < 4; mi++)
#pragma unroll
                for (int ni = 0; ni < 4; ni++)
                    mma_tf32(acc[mi][ni], af[mi], bf[ni]);
        }
        // no trailing sync: next iteration's leading sync protects stage reuse
    }

    // ---- epilogue ----
    const float* bias = bias_all + e * NOUT;
    float* obuf = (PHASE == 1) ? g_hbuf : g_ybuf;
    const size_t rowbase = (size_t)e * NTOK + (size_t)tm * 128;
#pragma unroll
    for (int mi = 0; mi < 4; mi++) {
        const int lr0 = wm * 64 + mi * 16 + grp;
        const int lr1 = lr0 + 8;
#pragma unroll
        for (int ni = 0; ni < 4; ni++) {
            const int col = tn * BN + wn * 32 + ni * 8 + tig * 2;
            const float bv0 = bias[col], bv1 = bias[col + 1];
            float v00 = acc[mi][ni][0] + bv0, v01 = acc[mi][ni][1] + bv1;
            float v10 = acc[mi][ni][2] + bv0, v11 = acc[mi][ni][3] + bv1;
            if (PHASE == 1) {
                v00 = tf32_round(gelu_tanh(v00)); v01 = tf32_round(gelu_tanh(v01));
                v10 = tf32_round(gelu_tanh(v10)); v11 = tf32_round(gelu_tanh(v11));
            }
            if (lr0 < rows)
                *(float2*)(obuf + (rowbase + lr0) * NOUT + col) = make_float2(v00, v01);
            if (lr1 < rows)
                *(float2*)(obuf + (rowbase + lr1) * NOUT + col) = make_float2(v10, v11);
        }
    }
}

// ---------------- stage 4: combine top-2 ----------------
__global__ void combine_kernel(float* __restrict__ out) {
    const int n = blockIdx.x;
    const int tid = threadIdx.x;                 // 256 threads, D/4 float4
    const int e0 = g_expi[n * 2], e1 = g_expi[n * 2 + 1];
    const int s0 = g_slot[n * 2], s1 = g_slot[n * 2 + 1];
    const float gg0 = g_gate[n * 2], gg1 = g_gate[n * 2 + 1];
    const float4* r0 = (const float4*)(g_ybuf + ((size_t)e0 * NTOK + s0) * DDIM);
    const float4* r1 = (const float4*)(g_ybuf + ((size_t)e1 * NTOK + s1) * DDIM);
    float4* o = (float4*)(out + (size_t)n * DDIM);
    float4 a = r0[tid], b = r1[tid];
    o[tid] = make_float4(gg0 * a.x + gg1 * b.x, gg0 * a.y + gg1 * b.y,
                         gg0 * a.z + gg1 * b.z, gg0 * a.w + gg1 * b.w);
}

// ---------------- launch ----------------
extern "C" void kernel_launch(void* const* d_in, const int* in_sizes, int n_in,
                              void* d_out, int out_size) {
    const float* x  = (const float*)d_in[0];   // [N, D]
    const float* wg = (const float*)d_in[1];   // [D, E]
    const float* w1 = (const float*)d_in[2];   // [E, D, H]
    const float* b1 = (const float*)d_in[3];   // [E, H]
    const float* w2 = (const float*)d_in[4];   // [E, H, D]
    const float* b2 = (const float*)d_in[5];   // [E, D]
    float* out = (float*)d_out;

    cudaFuncSetAttribute(ffn_gemm_kernel<1>, cudaFuncAttributeMaxDynamicSharedMemorySize, SMEM_BYTES);
    cudaFuncSetAttribute(ffn_gemm_kernel<2>, cudaFuncAttributeMaxDynamicSharedMemorySize, SMEM_BYTES);

    zero_counts_kernel<<<1, NEXP>>>();
    gate_kernel<<<NTOK, 128>>>(x, wg);

    ffn_gemm_kernel<1><<<dim3(HDIM / 256, NTOK / 128, NEXP), 512, SMEM_BYTES>>>(x, w1, b1);
    ffn_gemm_kernel<2><<<dim3(DDIM / 256, NTOK / 128, NEXP), 512, SMEM_BYTES>>>(x, w2, b2);

    combine_kernel<<<NTOK, 256>>>(out);
}

// round 10
// speedup vs baseline: 1.0373x; 1.0373x over previous
#include <cuda_runtime.h>
#include <cstdint>

#define NTOK 4096
#define DDIM 1024
#define HDIM 2048
#define NEXP 8

// ---------------- scratch (static __device__, allocation-free) ----------------
__device__ float g_xr [(size_t)NTOK * DDIM];                // tf32-rounded x
__device__ float g_w1r[(size_t)NEXP * DDIM * HDIM];         // tf32-rounded w1
__device__ float g_w2r[(size_t)NEXP * HDIM * DDIM];         // tf32-rounded w2
__device__ float g_hbuf[(size_t)NEXP * NTOK * HDIM];        // gelu(h) per slot (tf32-rounded)
__device__ float g_ybuf[(size_t)NEXP * NTOK * DDIM];        // expert outputs
__device__ int   g_counts[NEXP];
__device__ int   g_tok [NEXP * NTOK];                       // expert -> token list
__device__ int   g_expi[NTOK * 2];
__device__ int   g_slot[NTOK * 2];
__device__ float g_gate[NTOK * 2];

// ---------------- helpers ----------------
__device__ __forceinline__ uint32_t tf32_bits(float v) {    // round-to-nearest tf32
    uint32_t r;
    asm("cvt.rna.tf32.f32 %0, %1;" : "=r"(r) : "f"(v));
    return r;
}
__device__ __forceinline__ float tf32_round(float v) { return __uint_as_float(tf32_bits(v)); }

__device__ __forceinline__ void cpasync16(void* s, const void* g) {
    uint32_t sa = (uint32_t)__cvta_generic_to_shared(s);
    asm volatile("cp.async.cg.shared.global [%0], [%1], 16;" :: "r"(sa), "l"(g));
}
__device__ __forceinline__ void cp_commit() { asm volatile("cp.async.commit_group;"); }
__device__ __forceinline__ void cp_wait2()  { asm volatile("cp.async.wait_group 2;"); }

__device__ __forceinline__ void mma_tf32(float* c, const uint32_t* a, const uint32_t* b) {
    asm volatile(
        "mma.sync.aligned.m16n8k8.row.col.f32.tf32.tf32.f32 "
        "{%0,%1,%2,%3}, {%4,%5,%6,%7}, {%8,%9}, {%0,%1,%2,%3};"
        : "+f"(c[0]), "+f"(c[1]), "+f"(c[2]), "+f"(c[3])
        : "r"(a[0]), "r"(a[1]), "r"(a[2]), "r"(a[3]), "r"(b[0]), "r"(b[1]));
}

// JAX default gelu: approximate=True (tanh form)
__device__ __forceinline__ float gelu_tanh(float v) {
    float t = tanhf(0.7978845608028654f * (v + 0.044715f * v * v * v));
    return 0.5f * v * (1.0f + t);
}

// ---------------- stage 0: zero counts ----------------
__global__ void zero_counts_kernel() {
    if (threadIdx.x < NEXP) g_counts[threadIdx.x] = 0;
}

// ---------------- stage 0b: tf32 pre-round (removes all CVT from GEMM mainloop) ----
__global__ void round_tf32_kernel(const float4* __restrict__ in, float4* __restrict__ outp, int n4) {
    int i = blockIdx.x * blockDim.x + threadIdx.x;
    if (i < n4) {
        float4 v = in[i];
        v.x = tf32_round(v.x); v.y = tf32_round(v.y);
        v.z = tf32_round(v.z); v.w = tf32_round(v.w);
        outp[i] = v;
    }
}

// ---------------- stage 1: gating (top-2 softmax + expert lists) ----------------
__global__ void gate_kernel(const float* __restrict__ x, const float* __restrict__ wg) {
    const int n = blockIdx.x;
    const int tid = threadIdx.x;                 // 128 threads
    const float* xr = x + (size_t)n * DDIM;

    float acc[NEXP];
#pragma unroll
    for (int e = 0; e < NEXP; e++) acc[e] = 0.0f;
    for (int d = tid; d < DDIM; d += 128) {
        float xv = xr[d];
        const float* w = wg + d * NEXP;
#pragma unroll
        for (int e = 0; e < NEXP; e++) acc[e] += xv * w[e];
    }
#pragma unroll
    for (int e = 0; e < NEXP; e++) {
#pragma unroll
        for (int o = 16; o > 0; o >>= 1) acc[e] += __shfl_xor_sync(0xffffffffu, acc[e], o);
    }
    __shared__ float sred[4][NEXP];
    const int wid = tid >> 5, lane = tid & 31;
    if (lane == 0) {
#pragma unroll
        for (int e = 0; e < NEXP; e++) sred[wid][e] = acc[e];
    }
    __syncthreads();
    if (tid == 0) {
        float lg[NEXP];
#pragma unroll
        for (int e = 0; e < NEXP; e++)
            lg[e] = sred[0][e] + sred[1][e] + sred[2][e] + sred[3][e];
        int i0 = 0;
#pragma unroll
        for (int e = 1; e < NEXP; e++) if (lg[e] > lg[i0]) i0 = e;
        int i1 = (i0 == 0) ? 1 : 0;
#pragma unroll
        for (int e = 0; e < NEXP; e++) if (e != i0 && lg[e] > lg[i1]) i1 = e;
        float e1 = __expf(lg[i1] - lg[i0]);
        float inv = 1.0f / (1.0f + e1);

        int s0 = atomicAdd(&g_counts[i0], 1);
        int s1 = atomicAdd(&g_counts[i1], 1);
        g_tok[i0 * NTOK + s0] = n;
        g_tok[i1 * NTOK + s1] = n;
        g_expi[n * 2 + 0] = i0;  g_slot[n * 2 + 0] = s0;  g_gate[n * 2 + 0] = inv;
        g_expi[n * 2 + 1] = i1;  g_slot[n * 2 + 1] = s1;  g_gate[n * 2 + 1] = e1 * inv;
    }
}

// ---------------- stages 2/3: grouped GEMM, tf32 mma.sync ----------------
// CTA tile 128(tokens) x 256(cols), BK=16, 4-stage cp.async pipeline.
// 256 threads = 8 warps in a 2x4 grid, 64x64 per warp (fewest LDS/SMSP).
// All operands pre-rounded to tf32 in memory: ZERO cvt in the mainloop
// (the issue-bound fix: LDS+CVT+HMMA was ~550 slots/SMSP/kt; now ~300).
// One __syncthreads per k-iter.

#define A_STRIDE 20          // floats per A smem row (pad: conflict-free frag loads)
#define B_STRIDE 264         // floats per B smem row (pad: conflict-free frag loads)
#define A_STAGE  (128 * A_STRIDE)            // 2560 floats
#define B_STAGE  (16 * B_STRIDE)             // 4224 floats
#define SMEM_FLOATS (4 * (A_STAGE + B_STAGE))
#define SMEM_BYTES  (SMEM_FLOATS * 4)        // 108,544 B

template <int PHASE>
__global__ void __launch_bounds__(256, 1) ffn_gemm_kernel(
    const float* __restrict__ x, const float* __restrict__ w_all,
    const float* __restrict__ bias_all) {
    constexpr int KD   = (PHASE == 1) ? DDIM : HDIM;
    constexpr int NOUT = (PHASE == 1) ? HDIM : DDIM;
    constexpr int KT   = KD / 16;
    constexpr int BN   = 256;

    const int e  = blockIdx.z;
    const int tm = blockIdx.y;
    const int tn = blockIdx.x;
    const int cnt = g_counts[e];
    if (tm * 128 >= cnt) return;
    const int rows = min(128, cnt - tm * 128);

    extern __shared__ float smem[];
    float* const Abase = smem;                       // 4 stages x A_STAGE
    float* const Bbase = smem + 4 * A_STAGE;         // 4 stages x B_STAGE

    const int tid  = threadIdx.x;
    const int lane = tid & 31, wid = tid >> 5;
    const int wm = wid >> 2, wn = wid & 3;           // 2 x 4 warp grid, 64x64 per warp
    const int grp = lane >> 2, tig = lane & 3;

    // ---- per-thread load assignments ----
    // A: 128 rows x 16 k-floats = 512 x 16B chunks; 2 per thread
    const float* ag[2];
    int aoff[2];
    const float* wsrc = w_all + (size_t)e * ((size_t)KD * NOUT);
#pragma unroll
    for (int j = 0; j < 2; j++) {
        const int linear = j * 256 + tid;
        const int ar = linear >> 2;                  // row 0..127
        const int ac = (linear & 3) * 4;             // k-float offset 0/4/8/12
        if (PHASE == 1) {
            const int tk = g_tok[e * NTOK + tm * 128 + ar];
            ag[j] = x + (size_t)tk * DDIM + ac;
        } else {
            ag[j] = g_hbuf + ((size_t)e * NTOK + tm * 128 + ar) * HDIM + ac;
        }
        aoff[j] = ar * A_STRIDE + ac;
    }
    // B: 16 k-rows x 256 cols = 1024 x 16B chunks; 4 per thread
    const float* bg[4];
    int boff[4];
#pragma unroll
    for (int j = 0; j < 4; j++) {
        const int linear = j * 256 + tid;
        const int br = linear >> 6;                  // k-row 0..15
        const int bc = (linear & 63) * 4;            // col offset 0..252
        bg[j]   = wsrc + (size_t)br * NOUT + (size_t)tn * BN + bc;
        boff[j] = br * B_STRIDE + bc;
    }

    auto issue = [&](int it, int stage) {
        float* As = Abase + stage * A_STAGE;
        float* Bs = Bbase + stage * B_STAGE;
#pragma unroll
        for (int j = 0; j < 2; j++) cpasync16(As + aoff[j], ag[j] + it * 16);
#pragma unroll
        for (int j = 0; j < 4; j++) cpasync16(Bs + boff[j], bg[j] + (size_t)it * 16 * NOUT);
    };

    float acc[4][8][4];
#pragma unroll
    for (int mi = 0; mi < 4; mi++)
#pragma unroll
        for (int ni = 0; ni < 8; ni++)
#pragma unroll
            for (int q = 0; q < 4; q++) acc[mi][ni][q] = 0.0f;

    // ---- prologue: 3 stages in flight ----
    issue(0, 0); cp_commit();
    issue(1, 1); cp_commit();
    issue(2, 2); cp_commit();

    for (int it = 0; it < KT; it++) {
        const int stage = it & 3;
        cp_wait2();                                  // stage `it` landed
        __syncthreads();                             // everyone done reading stage (it-1)&3
        if (it + 3 < KT) issue(it + 3, (it + 3) & 3);   // overwrites stage (it-1)&3: safe
        cp_commit();                                 // empty commit at tail keeps count math

        const float* As = Abase + stage * A_STAGE;
        const float* Bs = Bbase + stage * B_STAGE;
#pragma unroll
        for (int kk = 0; kk < 2; kk++) {
            uint32_t af[4][4], bf[8][2];
            const int c0 = kk * 8 + tig;
#pragma unroll
            for (int mi = 0; mi < 4; mi++) {
                const int r = wm * 64 + mi * 16 + grp;
                af[mi][0] = __float_as_uint(As[r * A_STRIDE + c0]);
                af[mi][1] = __float_as_uint(As[(r + 8) * A_STRIDE + c0]);
                af[mi][2] = __float_as_uint(As[r * A_STRIDE + c0 + 4]);
                af[mi][3] = __float_as_uint(As[(r + 8) * A_STRIDE + c0 + 4]);
            }
#pragma unroll
            for (int ni = 0; ni < 8; ni++) {
                const int nc = wn * 64 + ni * 8 + grp;
                bf[ni][0] = __float_as_uint(Bs[(kk * 8 + tig) * B_STRIDE + nc]);
                bf[ni][1] = __float_as_uint(Bs[(kk * 8 + 4 + tig) * B_STRIDE + nc]);
            }
#pragma unroll
            for (int mi = 0; mi < 4; mi++)
#pragma unroll
                for (int ni = 0; ni < 8; ni++)
                    mma_tf32(acc[mi][ni], af[mi], bf[ni]);
        }
        // no trailing sync: next iteration's leading sync protects stage reuse
    }

    // ---- epilogue ----
    const float* bias = bias_all + e * NOUT;
    float* obuf = (PHASE == 1) ? g_hbuf : g_ybuf;
    const size_t rowbase = (size_t)e * NTOK + (size_t)tm * 128;
#pragma unroll
    for (int mi = 0; mi < 4; mi++) {
        const int lr0 = wm * 64 + mi * 16 + grp;
        const int lr1 = lr0 + 8;
#pragma unroll
        for (int ni = 0; ni < 8; ni++) {
            const int col = tn * BN + wn * 64 + ni * 8 + tig * 2;
            const float bv0 = bias[col], bv1 = bias[col + 1];
            float v00 = acc[mi][ni][0] + bv0, v01 = acc[mi][ni][1] + bv1;
            float v10 = acc[mi][ni][2] + bv0, v11 = acc[mi][ni][3] + bv1;
            if (PHASE == 1) {   // h written tf32-rounded -> phase 2 needs no CVT
                v00 = tf32_round(gelu_tanh(v00)); v01 = tf32_round(gelu_tanh(v01));
                v10 = tf32_round(gelu_tanh(v10)); v11 = tf32_round(gelu_tanh(v11));
            }
            if (lr0 < rows)
                *(float2*)(obuf + (rowbase + lr0) * NOUT + col) = make_float2(v00, v01);
            if (lr1 < rows)
                *(float2*)(obuf + (rowbase + lr1) * NOUT + col) = make_float2(v10, v11);
        }
    }
}

// ---------------- stage 4: combine top-2 ----------------
__global__ void combine_kernel(float* __restrict__ out) {
    const int n = blockIdx.x;
    const int tid = threadIdx.x;                 // 256 threads, D/4 float4
    const int e0 = g_expi[n * 2], e1 = g_expi[n * 2 + 1];
    const int s0 = g_slot[n * 2], s1 = g_slot[n * 2 + 1];
    const float gg0 = g_gate[n * 2], gg1 = g_gate[n * 2 + 1];
    const float4* r0 = (const float4*)(g_ybuf + ((size_t)e0 * NTOK + s0) * DDIM);
    const float4* r1 = (const float4*)(g_ybuf + ((size_t)e1 * NTOK + s1) * DDIM);
    float4* o = (float4*)(out + (size_t)n * DDIM);
    float4 a = r0[tid], b = r1[tid];
    o[tid] = make_float4(gg0 * a.x + gg1 * b.x, gg0 * a.y + gg1 * b.y,
                         gg0 * a.z + gg1 * b.z, gg0 * a.w + gg1 * b.w);
}

// ---------------- launch ----------------
extern "C" void kernel_launch(void* const* d_in, const int* in_sizes, int n_in,
                              void* d_out, int out_size) {
    const float* x  = (const float*)d_in[0];   // [N, D]
    const float* wg = (const float*)d_in[1];   // [D, E]
    const float* w1 = (const float*)d_in[2];   // [E, D, H]
    const float* b1 = (const float*)d_in[3];   // [E, H]
    const float* w2 = (const float*)d_in[4];   // [E, H, D]
    const float* b2 = (const float*)d_in[5];   // [E, D]
    float* out = (float*)d_out;

    float* xr;  cudaGetSymbolAddress((void**)&xr,  g_xr);
    float* w1r; cudaGetSymbolAddress((void**)&w1r, g_w1r);
    float* w2r; cudaGetSymbolAddress((void**)&w2r, g_w2r);

    cudaFuncSetAttribute(ffn_gemm_kernel<1>, cudaFuncAttributeMaxDynamicSharedMemorySize, SMEM_BYTES);
    cudaFuncSetAttribute(ffn_gemm_kernel<2>, cudaFuncAttributeMaxDynamicSharedMemorySize, SMEM_BYTES);

    zero_counts_kernel<<<1, NEXP>>>();
    gate_kernel<<<NTOK, 128>>>(x, wg);

    {   // pre-round: removes every CVT from both GEMM mainloops
        int n4 = NTOK * DDIM / 4;
        round_tf32_kernel<<<(n4 + 255) / 256, 256>>>((const float4*)x, (float4*)xr, n4);
        int m4 = NEXP * DDIM * HDIM / 4;
        round_tf32_kernel<<<(m4 + 255) / 256, 256>>>((const float4*)w1, (float4*)w1r, m4);
        round_tf32_kernel<<<(m4 + 255) / 256, 256>>>((const float4*)w2, (float4*)w2r, m4);
    }

    ffn_gemm_kernel<1><<<dim3(HDIM / 256, NTOK / 128, NEXP), 256, SMEM_BYTES>>>(xr, w1r, b1);
    ffn_gemm_kernel<2><<<dim3(DDIM / 256, NTOK / 128, NEXP), 256, SMEM_BYTES>>>(xr, w2r, b2);

    combine_kernel<<<NTOK, 256>>>(out);
}